// round 12
// baseline (speedup 1.0000x reference)
#include <cuda_runtime.h>
#include <math.h>
#include <stdint.h>

#define NB   4
#define HH   128
#define WW   128
#define CC   128
#define GG   8
#define GC   16
#define KK   9
#define NTOK (NB * HH * WW)   // 65536
#define HID  512
#define NOM  256              // padded offset(144)+mask(72) combined width
#define EPS  1e-5f

// ---------------- scratch (device globals; no allocation allowed) ------------
__device__ float g_xn [NTOK * CC];
__device__ float g_xp [NTOK * CC];
__device__ float g_x1 [NTOK * CC];
__device__ float g_om [NTOK * NOM];
__device__ float g_y  [NTOK * CC];
__device__ float g_x2 [NTOK * CC];
__device__ float g_h  [NTOK * CC];
__device__ float g_h1 [NTOK * HID];
// transposed weights [N][K]
__device__ float g_inT  [CC * CC];
__device__ float g_outT [CC * CC];
__device__ float g_fc1T [HID * CC];
__device__ float g_fc2T [CC * HID];
__device__ float g_wcatT[NOM * CC];
__device__ float g_bcat [NOM];

__device__ __forceinline__ float gelu_exact(float x) {
    return 0.5f * x * (1.0f + erff(x * 0.70710678118654752f));
}

__device__ __forceinline__ void mma_tf32(float c[4], const uint32_t a[4], const uint32_t b[2]) {
    asm volatile(
        "mma.sync.aligned.m16n8k8.row.col.f32.tf32.tf32.f32 "
        "{%0,%1,%2,%3}, {%4,%5,%6,%7}, {%8,%9}, {%0,%1,%2,%3};"
        : "+f"(c[0]), "+f"(c[1]), "+f"(c[2]), "+f"(c[3])
        : "r"(a[0]), "r"(a[1]), "r"(a[2]), "r"(a[3]), "r"(b[0]), "r"(b[1]));
}

__device__ __forceinline__ void ldsm_x4(uint32_t& r0, uint32_t& r1, uint32_t& r2, uint32_t& r3,
                                        uint32_t addr) {
    asm volatile("ldmatrix.sync.aligned.m8n8.x4.shared.b16 {%0,%1,%2,%3}, [%4];"
                 : "=r"(r0), "=r"(r1), "=r"(r2), "=r"(r3) : "r"(addr));
}

__device__ __forceinline__ void cp_async16(uint32_t dst_smem, const void* src) {
    asm volatile("cp.async.cg.shared.global [%0], [%1], 16;" :: "r"(dst_smem), "l"(src));
}
__device__ __forceinline__ void cp_commit() { asm volatile("cp.async.commit_group;"); }
template <int N> __device__ __forceinline__ void cp_wait() {
    asm volatile("cp.async.wait_group %0;" :: "n"(N));
}

// ------------- unified weight prep: all transposes + offmask pack -----------
// ranges: [0,16384) in_w; [16384,32768) out_w; [32768,98304) fc1_w;
//         [98304,163840) fc2_w; [163840,196608) wcatT; [196608,196864) bcat
__global__ __launch_bounds__(256) void prep_weights_kernel(
    const float* __restrict__ in_w,  const float* __restrict__ out_w,
    const float* __restrict__ fc1_w, const float* __restrict__ fc2_w,
    const float* __restrict__ off_w, const float* __restrict__ off_b,
    const float* __restrict__ mask_w, const float* __restrict__ mask_b,
    float* __restrict__ inT,  float* __restrict__ outT,
    float* __restrict__ fc1T, float* __restrict__ fc2T,
    float* __restrict__ wcatT, float* __restrict__ bcat)
{
    const int idx = blockIdx.x * 256 + threadIdx.x;
    if (idx < 16384) {
        const int k = idx >> 7, n = idx & 127;
        inT[n * 128 + k] = in_w[idx];
    } else if (idx < 32768) {
        const int l = idx - 16384, k = l >> 7, n = l & 127;
        outT[n * 128 + k] = out_w[l];
    } else if (idx < 98304) {
        const int l = idx - 32768, k = l / 512, n = l % 512;
        fc1T[n * 128 + k] = fc1_w[l];
    } else if (idx < 163840) {
        const int l = idx - 98304, k = l >> 7, n = l & 127;
        fc2T[n * 512 + k] = fc2_w[l];
    } else if (idx < 196608) {
        const int l = idx - 163840, j = l >> 7, k = l & 127;
        float v = 0.0f;
        if (j < 144)      v = off_w[k * 144 + j];
        else if (j < 216) v = mask_w[k * 72 + (j - 144)];
        wcatT[j * 128 + k] = v;
    } else if (idx < 196864) {
        const int j = idx - 196608;
        float bv = 0.0f;
        if (j < 144)      bv = off_b[j];
        else if (j < 216) bv = mask_b[j - 144];
        bcat[j] = bv;
    }
}

// -------- LayerNorm, warp per token, float4, shfl-only reduction ------------
__global__ __launch_bounds__(256) void ln_v4_kernel(
    const float* __restrict__ in, const float* __restrict__ g,
    const float* __restrict__ b, float* __restrict__ out)
{
    const int warp = threadIdx.x >> 5;
    const int lane = threadIdx.x & 31;
    const int tok  = blockIdx.x * 8 + warp;

    const float4 v = *(const float4*)&in[(size_t)tok * CC + lane * 4];
    float s  = v.x + v.y + v.z + v.w;
    float s2 = v.x * v.x + v.y * v.y + v.z * v.z + v.w * v.w;
    #pragma unroll
    for (int o = 16; o > 0; o >>= 1) {
        s  += __shfl_xor_sync(0xffffffffu, s,  o);
        s2 += __shfl_xor_sync(0xffffffffu, s2, o);
    }
    const float mean = s * (1.0f / CC);
    const float var  = s2 * (1.0f / CC) - mean * mean;
    const float rstd = rsqrtf(var + EPS);
    const float4 gg = *(const float4*)&g[lane * 4];
    const float4 bb = *(const float4*)&b[lane * 4];
    float4 o4;
    o4.x = (v.x - mean) * rstd * gg.x + bb.x;
    o4.y = (v.y - mean) * rstd * gg.y + bb.y;
    o4.z = (v.z - mean) * rstd * gg.z + bb.z;
    o4.w = (v.w - mean) * rstd * gg.w + bb.w;
    *(float4*)&out[(size_t)tok * CC + lane * 4] = o4;
}

// ------ dwconv3x3 + LN + GELU: warp per token, float4, interior fast path ---
__global__ __launch_bounds__(256) void dwconv_ln_gelu_v4_kernel(
    const float* __restrict__ xn, const float* __restrict__ dwk,
    const float* __restrict__ dwb, const float* __restrict__ lg,
    const float* __restrict__ lb, float* __restrict__ out)
{
    const int warp = threadIdx.x >> 5;
    const int lane = threadIdx.x & 31;
    const int tok  = blockIdx.x * 8 + warp;
    const int hw = tok & (HH * WW - 1);
    const int h = hw >> 7, w = hw & 127;
    const int c4 = lane * 4;

    float4 acc = *(const float4*)&dwb[c4];
    const float* p = xn + (size_t)tok * CC + c4;
    const float* kw = dwk + c4;

    if (h >= 1 && h <= HH - 2 && w >= 1 && w <= WW - 2) {
        #pragma unroll
        for (int ky = 0; ky < 3; ky++) {
            #pragma unroll
            for (int kx = 0; kx < 3; kx++) {
                const int doff = ((ky - 1) * WW + (kx - 1)) * CC;
                const float4 v = *(const float4*)(p + doff);
                const float4 k = *(const float4*)(kw + (ky * 3 + kx) * CC);
                acc.x = fmaf(v.x, k.x, acc.x);
                acc.y = fmaf(v.y, k.y, acc.y);
                acc.z = fmaf(v.z, k.z, acc.z);
                acc.w = fmaf(v.w, k.w, acc.w);
            }
        }
    } else {
        #pragma unroll
        for (int ky = 0; ky < 3; ky++) {
            const int yy = h + ky - 1;
            if (yy < 0 || yy >= HH) continue;
            #pragma unroll
            for (int kx = 0; kx < 3; kx++) {
                const int xx = w + kx - 1;
                if (xx < 0 || xx >= WW) continue;
                const int doff = ((ky - 1) * WW + (kx - 1)) * CC;
                const float4 v = *(const float4*)(p + doff);
                const float4 k = *(const float4*)(kw + (ky * 3 + kx) * CC);
                acc.x = fmaf(v.x, k.x, acc.x);
                acc.y = fmaf(v.y, k.y, acc.y);
                acc.z = fmaf(v.z, k.z, acc.z);
                acc.w = fmaf(v.w, k.w, acc.w);
            }
        }
    }

    float s  = acc.x + acc.y + acc.z + acc.w;
    float s2 = acc.x * acc.x + acc.y * acc.y + acc.z * acc.z + acc.w * acc.w;
    #pragma unroll
    for (int o = 16; o > 0; o >>= 1) {
        s  += __shfl_xor_sync(0xffffffffu, s,  o);
        s2 += __shfl_xor_sync(0xffffffffu, s2, o);
    }
    const float mean = s * (1.0f / CC);
    const float var  = s2 * (1.0f / CC) - mean * mean;
    const float rstd = rsqrtf(var + EPS);
    const float4 gg = *(const float4*)&lg[c4];
    const float4 bb = *(const float4*)&lb[c4];
    float4 o4;
    o4.x = gelu_exact((acc.x - mean) * rstd * gg.x + bb.x);
    o4.y = gelu_exact((acc.y - mean) * rstd * gg.y + bb.y);
    o4.z = gelu_exact((acc.z - mean) * rstd * gg.z + bb.z);
    o4.w = gelu_exact((acc.w - mean) * rstd * gg.w + bb.w);
    *(float4*)&out[(size_t)tok * CC + c4] = o4;
}

// ---- tf32 GEMM: ldmatrix A AND B frags; BT is [N][K] -----------------------
// BM=128, BN=128, BK=32; 256 thr = 8 warps (2 M x 4 N), warp tile 64x32.
// Both smem tiles [row][k] stride 36 (rows: A=m 128, B=n 128).
#define TS_STRIDE 36
#define T_BUF (128 * TS_STRIDE)
#define GEMM_SMEM_BYTES (4 * T_BUF * 4)

__global__ __launch_bounds__(256) void gemm_tf32_db_kernel(
    const float* __restrict__ A, const float* __restrict__ BT,
    const float* __restrict__ bias, const float* __restrict__ res,
    float* __restrict__ C, int M, int N, int K, int act)
{
    extern __shared__ float smem[];
    const uint32_t s_base = (uint32_t)__cvta_generic_to_shared(smem);
    const uint32_t sA_u = s_base;                    // [2][128][36] A
    const uint32_t sB_u = s_base + 2 * T_BUF * 4;    // [2][128][36] B ([n][k])

    const int tid  = threadIdx.x;
    const int warp = tid >> 5;
    const int lane = tid & 31;
    const int grp  = lane >> 2;
    const int t4   = lane & 3;
    const int wm   = warp >> 2;     // 0..1 -> 64 M rows
    const int wn   = warp & 3;      // 0..3 -> 32 N cols
    const int brow = blockIdx.y * 128;
    const int bcol = blockIdx.x * 128;
    const int KT = K >> 5;

    // ldmatrix A lane-role offsets (validated: identical rel_err)
    const int a_row = ((lane >> 3) & 1) * 8 + (lane & 7);  // mats 0/1: rows +0/+8
    const int a_col = (lane >> 4) * 4;                     // mats 2/3: k+4

    auto load_tile = [&](int kt, int buf) {
        const int k0 = kt << 5;
        #pragma unroll
        for (int it = 0; it < 4; it++) {
            const int idx = it * 256 + tid;
            const int r = idx >> 3, c = idx & 7;
            cp_async16(sA_u + (buf * T_BUF + r * TS_STRIDE + c * 4) * 4,
                       &A[(size_t)(brow + r) * K + k0 + c * 4]);
        }
        #pragma unroll
        for (int it = 0; it < 4; it++) {
            const int idx = it * 256 + tid;
            const int r = idx >> 3, c = idx & 7;
            cp_async16(sB_u + (buf * T_BUF + r * TS_STRIDE + c * 4) * 4,
                       &BT[(size_t)(bcol + r) * K + k0 + c * 4]);
        }
        cp_commit();
    };

    float acc[4][4][4];
    #pragma unroll
    for (int i = 0; i < 4; i++)
        #pragma unroll
        for (int j = 0; j < 4; j++)
            #pragma unroll
            for (int q = 0; q < 4; q++) acc[i][j][q] = 0.0f;

    load_tile(0, 0);

    for (int kt = 0; kt < KT; kt++) {
        if (kt + 1 < KT) { load_tile(kt + 1, (kt + 1) & 1); cp_wait<1>(); }
        else             { cp_wait<0>(); }
        __syncthreads();

        const uint32_t Ab_u = sA_u + ((kt & 1) * T_BUF) * 4;
        const uint32_t Bb_u = sB_u + ((kt & 1) * T_BUF) * 4;
        const int n0 = wn * 32;

        #pragma unroll
        for (int kk = 0; kk < 4; kk++) {
            const int kb = kk * 8;
            uint32_t af[4][4], bf[4][2];
            #pragma unroll
            for (int i = 0; i < 4; i++) {
                const int m0 = wm * 64 + i * 16;
                ldsm_x4(af[i][0], af[i][1], af[i][2], af[i][3],
                        Ab_u + ((m0 + a_row) * TS_STRIDE + kb + a_col) * 4);
            }
            // B frags: mats 0..3 <-> n-offsets 0,8,16,24; two x4 for k halves
            ldsm_x4(bf[0][0], bf[1][0], bf[2][0], bf[3][0],
                    Bb_u + ((n0 + lane) * TS_STRIDE + kb) * 4);
            ldsm_x4(bf[0][1], bf[1][1], bf[2][1], bf[3][1],
                    Bb_u + ((n0 + lane) * TS_STRIDE + kb + 4) * 4);
            #pragma unroll
            for (int i = 0; i < 4; i++)
                #pragma unroll
                for (int j = 0; j < 4; j++)
                    mma_tf32(acc[i][j], af[i], bf[j]);
        }
        __syncthreads();
    }

    #pragma unroll
    for (int i = 0; i < 4; i++) {
        const int r0 = brow + wm * 64 + i * 16 + grp;
        #pragma unroll
        for (int j = 0; j < 4; j++) {
            const int col = bcol + wn * 32 + j * 8 + 2 * t4;
            const float b0 = bias[col], b1 = bias[col + 1];
            #pragma unroll
            for (int half = 0; half < 2; half++) {
                const int r = r0 + half * 8;
                float v0 = acc[i][j][half * 2 + 0] + b0;
                float v1 = acc[i][j][half * 2 + 1] + b1;
                if (act == 1) { v0 = gelu_exact(v0); v1 = gelu_exact(v1); }
                if (res) {
                    const float2 rr = *(const float2*)&res[(size_t)r * N + col];
                    v0 += rr.x; v1 += rr.y;
                }
                *(float2*)&C[(size_t)r * N + col] = make_float2(v0, v1);
            }
        }
    }
}

// ------- deformable sampling + fused softmax; 1 warp per token, float4 ------
__global__ __launch_bounds__(128) void dcn_sample_kernel(
    const float* __restrict__ xp, const float* __restrict__ om,
    float* __restrict__ y)
{
    const int tt   = threadIdx.x >> 5;
    const int lane = threadIdx.x & 31;
    const int tok  = blockIdx.x * 4 + tt;
    const int n  = tok / (HH * WW);
    const int hw = tok % (HH * WW);
    const int h = hw / WW, w = hw % WW;

    __shared__ float s_om[4][216];
    const float* src = om + (size_t)tok * NOM;
    for (int i = lane; i < 216; i += 32) s_om[tt][i] = src[i];
    __syncwarp();

    if (lane < GG) {
        float* p = &s_om[tt][144 + lane * KK];
        float mx = -1e30f;
        #pragma unroll
        for (int k = 0; k < KK; k++) mx = fmaxf(mx, p[k]);
        float s = 0.0f, e[KK];
        #pragma unroll
        for (int k = 0; k < KK; k++) { e[k] = __expf(p[k] - mx); s += e[k]; }
        const float inv = 1.0f / s;
        #pragma unroll
        for (int k = 0; k < KK; k++) p[k] = e[k] * inv;
    }
    __syncwarp();

    const int g  = lane >> 2;
    const int c4 = lane & 3;
    const float* base = xp + ((size_t)n * HH * WW) * CC + g * GC + c4 * 4;
    float4 acc = make_float4(0.f, 0.f, 0.f, 0.f);

    #pragma unroll
    for (int k = 0; k < KK; k++) {
        const float ox = s_om[tt][(g * KK + k) * 2 + 0];
        const float oy = s_om[tt][(g * KK + k) * 2 + 1];
        const float mw = s_om[tt][144 + g * KK + k];
        const float px = (float)(w + 1 + (k / 3) - 1) + ox;
        const float py = (float)(h + 1 + (k % 3) - 1) + oy;
        const float x0f = floorf(px), y0f = floorf(py);
        const float tx = px - x0f, ty = py - y0f;
        const int x0 = (int)x0f, y0 = (int)y0f;

        const bool yi0 = (y0 >= 1) & (y0 <= HH);
        const bool yi1 = (y0 + 1 >= 1) & (y0 + 1 <= HH);
        const bool xi0 = (x0 >= 1) & (x0 <= WW);
        const bool xi1 = (x0 + 1 >= 1) & (x0 + 1 <= WW);

        float4 v00 = make_float4(0,0,0,0), v01 = v00, v10 = v00, v11 = v00;
        if (yi0 & xi0) v00 = *(const float4*)&base[((size_t)(y0 - 1) * WW + (x0 - 1)) * CC];
        if (yi0 & xi1) v01 = *(const float4*)&base[((size_t)(y0 - 1) * WW + (x0    )) * CC];
        if (yi1 & xi0) v10 = *(const float4*)&base[((size_t)(y0    ) * WW + (x0 - 1)) * CC];
        if (yi1 & xi1) v11 = *(const float4*)&base[((size_t)(y0    ) * WW + (x0    )) * CC];

        const float w00 = mw * (1.f - ty) * (1.f - tx);
        const float w01 = mw * (1.f - ty) * tx;
        const float w10 = mw * ty * (1.f - tx);
        const float w11 = mw * ty * tx;
        acc.x += w00 * v00.x + w01 * v01.x + w10 * v10.x + w11 * v11.x;
        acc.y += w00 * v00.y + w01 * v01.y + w10 * v10.y + w11 * v11.y;
        acc.z += w00 * v00.z + w01 * v01.z + w10 * v10.z + w11 * v11.z;
        acc.w += w00 * v00.w + w01 * v01.w + w10 * v10.w + w11 * v11.w;
    }
    *(float4*)&y[(size_t)tok * CC + g * GC + c4 * 4] = acc;
}

// ---------------------------------------------------------------------------
extern "C" void kernel_launch(void* const* d_in, const int* in_sizes, int n_in,
                              void* d_out, int out_size)
{
    const float* x      = (const float*)d_in[0];
    const float* ln1_g  = (const float*)d_in[1];
    const float* ln1_b  = (const float*)d_in[2];
    const float* in_w   = (const float*)d_in[3];
    const float* in_b   = (const float*)d_in[4];
    const float* dw_k   = (const float*)d_in[5];
    const float* dw_b   = (const float*)d_in[6];
    const float* dwln_g = (const float*)d_in[7];
    const float* dwln_b = (const float*)d_in[8];
    const float* off_w  = (const float*)d_in[9];
    const float* off_b  = (const float*)d_in[10];
    const float* mask_w = (const float*)d_in[11];
    const float* mask_b = (const float*)d_in[12];
    const float* out_w  = (const float*)d_in[13];
    const float* out_b  = (const float*)d_in[14];
    const float* ln2_g  = (const float*)d_in[15];
    const float* ln2_b  = (const float*)d_in[16];
    const float* fc1_w  = (const float*)d_in[17];
    const float* fc1_b  = (const float*)d_in[18];
    const float* fc2_w  = (const float*)d_in[19];
    const float* fc2_b  = (const float*)d_in[20];
    float* out = (float*)d_out;

    float *xn, *xp, *x1, *omp, *yp, *x2, *hp, *h1;
    float *inT, *outT, *fc1T, *fc2T, *wcatT, *bcat;
    cudaGetSymbolAddress((void**)&xn,    g_xn);
    cudaGetSymbolAddress((void**)&xp,    g_xp);
    cudaGetSymbolAddress((void**)&x1,    g_x1);
    cudaGetSymbolAddress((void**)&omp,   g_om);
    cudaGetSymbolAddress((void**)&yp,    g_y);
    cudaGetSymbolAddress((void**)&x2,    g_x2);
    cudaGetSymbolAddress((void**)&hp,    g_h);
    cudaGetSymbolAddress((void**)&h1,    g_h1);
    cudaGetSymbolAddress((void**)&inT,   g_inT);
    cudaGetSymbolAddress((void**)&outT,  g_outT);
    cudaGetSymbolAddress((void**)&fc1T,  g_fc1T);
    cudaGetSymbolAddress((void**)&fc2T,  g_fc2T);
    cudaGetSymbolAddress((void**)&wcatT, g_wcatT);
    cudaGetSymbolAddress((void**)&bcat,  g_bcat);

    static bool attr_done = false;
    if (!attr_done) {
        cudaFuncSetAttribute(gemm_tf32_db_kernel,
                             cudaFuncAttributeMaxDynamicSharedMemorySize,
                             GEMM_SMEM_BYTES);
        attr_done = true;
    }

    const int MROW = NTOK / 128;
    const dim3 gemm128(1, MROW);
    const dim3 gemm256(2, MROW);
    const dim3 gemm512(4, MROW);

    // 0. unified weight prep: 196864 items -> 769 blocks
    prep_weights_kernel<<<769, 256>>>(in_w, out_w, fc1_w, fc2_w,
                                      off_w, off_b, mask_w, mask_b,
                                      inT, outT, fc1T, fc2T, wcatT, bcat);

    ln_v4_kernel<<<NTOK / 8, 256>>>(x, ln1_g, ln1_b, xn);
    gemm_tf32_db_kernel<<<gemm128, 256, GEMM_SMEM_BYTES>>>(xn, inT, in_b, nullptr, xp, NTOK, CC, CC, 0);
    dwconv_ln_gelu_v4_kernel<<<NTOK / 8, 256>>>(xn, dw_k, dw_b, dwln_g, dwln_b, x1);
    gemm_tf32_db_kernel<<<gemm256, 256, GEMM_SMEM_BYTES>>>(x1, wcatT, bcat, nullptr, omp, NTOK, NOM, CC, 0);
    dcn_sample_kernel<<<NTOK / 4, 128>>>(xp, omp, yp);
    gemm_tf32_db_kernel<<<gemm128, 256, GEMM_SMEM_BYTES>>>(yp, outT, out_b, x, x2, NTOK, CC, CC, 0);
    ln_v4_kernel<<<NTOK / 8, 256>>>(x2, ln2_g, ln2_b, hp);
    gemm_tf32_db_kernel<<<gemm512, 256, GEMM_SMEM_BYTES>>>(hp, fc1T, fc1_b, nullptr, h1, NTOK, HID, CC, 1);
    gemm_tf32_db_kernel<<<gemm128, 256, GEMM_SMEM_BYTES>>>(h1, fc2T, fc2_b, x2, out, NTOK, CC, HID, 0);
}

// round 13
// speedup vs baseline: 1.0765x; 1.0765x over previous
#include <cuda_runtime.h>
#include <math.h>
#include <stdint.h>

#define NB   4
#define HH   128
#define WW   128
#define CC   128
#define GG   8
#define GC   16
#define KK   9
#define NTOK (NB * HH * WW)   // 65536
#define HID  512
#define NOM  256              // padded offset(144)+mask(72) combined width
#define EPS  1e-5f

// ---------------- scratch (device globals; no allocation allowed) ------------
__device__ float g_xn [NTOK * CC];
__device__ float g_xp [NTOK * CC];
__device__ float g_x1 [NTOK * CC];
__device__ float g_om [NTOK * NOM];
__device__ float g_y  [NTOK * CC];
__device__ float g_x2 [NTOK * CC];
__device__ float g_h  [NTOK * CC];
__device__ float g_h1 [NTOK * HID];
__device__ float g_wcat[CC * NOM];       // [K=128][256] packed off_w|mask_w|0
__device__ float g_bcat[NOM];

__device__ __forceinline__ float gelu_exact(float x) {
    return 0.5f * x * (1.0f + erff(x * 0.70710678118654752f));
}

__device__ __forceinline__ void mma_tf32(float c[4], const uint32_t a[4], const uint32_t b[2]) {
    asm volatile(
        "mma.sync.aligned.m16n8k8.row.col.f32.tf32.tf32.f32 "
        "{%0,%1,%2,%3}, {%4,%5,%6,%7}, {%8,%9}, {%0,%1,%2,%3};"
        : "+f"(c[0]), "+f"(c[1]), "+f"(c[2]), "+f"(c[3])
        : "r"(a[0]), "r"(a[1]), "r"(a[2]), "r"(a[3]), "r"(b[0]), "r"(b[1]));
}

__device__ __forceinline__ void ldsm_x4(uint32_t& r0, uint32_t& r1, uint32_t& r2, uint32_t& r3,
                                        uint32_t addr) {
    asm volatile("ldmatrix.sync.aligned.m8n8.x4.shared.b16 {%0,%1,%2,%3}, [%4];"
                 : "=r"(r0), "=r"(r1), "=r"(r2), "=r"(r3) : "r"(addr));
}

__device__ __forceinline__ void cp_async16(uint32_t dst_smem, const void* src) {
    asm volatile("cp.async.cg.shared.global [%0], [%1], 16;" :: "r"(dst_smem), "l"(src));
}
__device__ __forceinline__ void cp_commit() { asm volatile("cp.async.commit_group;"); }
template <int N> __device__ __forceinline__ void cp_wait() {
    asm volatile("cp.async.wait_group %0;" :: "n"(N));
}

// ---------------- weight-packing prep: wcat = [off_w | mask_w | 0] ----------
__global__ __launch_bounds__(256) void prep_offmask_kernel(
    const float* __restrict__ off_w, const float* __restrict__ off_b,
    const float* __restrict__ mask_w, const float* __restrict__ mask_b,
    float* __restrict__ wcat, float* __restrict__ bcat)
{
    const int k = blockIdx.x;
    const int j = threadIdx.x;
    float v = 0.0f;
    if (j < 144)      v = off_w[k * 144 + j];
    else if (j < 216) v = mask_w[k * 72 + (j - 144)];
    wcat[k * NOM + j] = v;
    if (k == 0) {
        float bv = 0.0f;
        if (j < 144)      bv = off_b[j];
        else if (j < 216) bv = mask_b[j - 144];
        bcat[j] = bv;
    }
}

// -------- LayerNorm, warp per token, float4, shfl-only reduction ------------
__global__ __launch_bounds__(256) void ln_v4_kernel(
    const float* __restrict__ in, const float* __restrict__ g,
    const float* __restrict__ b, float* __restrict__ out)
{
    const int warp = threadIdx.x >> 5;
    const int lane = threadIdx.x & 31;
    const int tok  = blockIdx.x * 8 + warp;

    const float4 v = *(const float4*)&in[(size_t)tok * CC + lane * 4];
    float s  = v.x + v.y + v.z + v.w;
    float s2 = v.x * v.x + v.y * v.y + v.z * v.z + v.w * v.w;
    #pragma unroll
    for (int o = 16; o > 0; o >>= 1) {
        s  += __shfl_xor_sync(0xffffffffu, s,  o);
        s2 += __shfl_xor_sync(0xffffffffu, s2, o);
    }
    const float mean = s * (1.0f / CC);
    const float var  = s2 * (1.0f / CC) - mean * mean;
    const float rstd = rsqrtf(var + EPS);
    const float4 gg = *(const float4*)&g[lane * 4];
    const float4 bb = *(const float4*)&b[lane * 4];
    float4 o4;
    o4.x = (v.x - mean) * rstd * gg.x + bb.x;
    o4.y = (v.y - mean) * rstd * gg.y + bb.y;
    o4.z = (v.z - mean) * rstd * gg.z + bb.z;
    o4.w = (v.w - mean) * rstd * gg.w + bb.w;
    *(float4*)&out[(size_t)tok * CC + lane * 4] = o4;
}

// ------ dwconv3x3 + LN + GELU: warp per token, float4, interior fast path ---
__global__ __launch_bounds__(256) void dwconv_ln_gelu_v4_kernel(
    const float* __restrict__ xn, const float* __restrict__ dwk,
    const float* __restrict__ dwb, const float* __restrict__ lg,
    const float* __restrict__ lb, float* __restrict__ out)
{
    const int warp = threadIdx.x >> 5;
    const int lane = threadIdx.x & 31;
    const int tok  = blockIdx.x * 8 + warp;
    const int hw = tok & (HH * WW - 1);
    const int h = hw >> 7, w = hw & 127;
    const int c4 = lane * 4;

    float4 acc = *(const float4*)&dwb[c4];
    const float* p = xn + (size_t)tok * CC + c4;
    const float* kw = dwk + c4;

    if (h >= 1 && h <= HH - 2 && w >= 1 && w <= WW - 2) {
        #pragma unroll
        for (int ky = 0; ky < 3; ky++) {
            #pragma unroll
            for (int kx = 0; kx < 3; kx++) {
                const int doff = ((ky - 1) * WW + (kx - 1)) * CC;
                const float4 v = *(const float4*)(p + doff);
                const float4 k = *(const float4*)(kw + (ky * 3 + kx) * CC);
                acc.x = fmaf(v.x, k.x, acc.x);
                acc.y = fmaf(v.y, k.y, acc.y);
                acc.z = fmaf(v.z, k.z, acc.z);
                acc.w = fmaf(v.w, k.w, acc.w);
            }
        }
    } else {
        #pragma unroll
        for (int ky = 0; ky < 3; ky++) {
            const int yy = h + ky - 1;
            if (yy < 0 || yy >= HH) continue;
            #pragma unroll
            for (int kx = 0; kx < 3; kx++) {
                const int xx = w + kx - 1;
                if (xx < 0 || xx >= WW) continue;
                const int doff = ((ky - 1) * WW + (kx - 1)) * CC;
                const float4 v = *(const float4*)(p + doff);
                const float4 k = *(const float4*)(kw + (ky * 3 + kx) * CC);
                acc.x = fmaf(v.x, k.x, acc.x);
                acc.y = fmaf(v.y, k.y, acc.y);
                acc.z = fmaf(v.z, k.z, acc.z);
                acc.w = fmaf(v.w, k.w, acc.w);
            }
        }
    }

    float s  = acc.x + acc.y + acc.z + acc.w;
    float s2 = acc.x * acc.x + acc.y * acc.y + acc.z * acc.z + acc.w * acc.w;
    #pragma unroll
    for (int o = 16; o > 0; o >>= 1) {
        s  += __shfl_xor_sync(0xffffffffu, s,  o);
        s2 += __shfl_xor_sync(0xffffffffu, s2, o);
    }
    const float mean = s * (1.0f / CC);
    const float var  = s2 * (1.0f / CC) - mean * mean;
    const float rstd = rsqrtf(var + EPS);
    const float4 gg = *(const float4*)&lg[c4];
    const float4 bb = *(const float4*)&lb[c4];
    float4 o4;
    o4.x = gelu_exact((acc.x - mean) * rstd * gg.x + bb.x);
    o4.y = gelu_exact((acc.y - mean) * rstd * gg.y + bb.y);
    o4.z = gelu_exact((acc.z - mean) * rstd * gg.z + bb.z);
    o4.w = gelu_exact((acc.w - mean) * rstd * gg.w + bb.w);
    *(float4*)&out[(size_t)tok * CC + c4] = o4;
}

// ---- tf32 GEMM (R11 config: ldmatrix A, LDS B) + optional fused-LN epilogue
// BM=128, BN=128, BK=32; 256 thr = 8 warps (2 M x 4 N), warp tile 64x32.
// A smem [m][k] stride 36; B smem [k][n] stride 136.
// act: 0 = none, 1 = gelu, 2 = (res add, write C=x2) + LN -> D (requires
//      N==128, gridDim.x==1, res != null).
#define AS_STRIDE 36
#define BS_STRIDE 136
#define A_BUF (128 * AS_STRIDE)
#define B_BUF (32 * BS_STRIDE)
#define GEMM_SMEM_BYTES ((2 * A_BUF + 2 * B_BUF) * 4)   // 71680
#define SX_STRIDE 132                                   // 128*132*4 = 67584 <= 71680

__global__ __launch_bounds__(256) void gemm_tf32_db_kernel(
    const float* __restrict__ A, const float* __restrict__ B,
    const float* __restrict__ bias, const float* __restrict__ res,
    float* __restrict__ C, float* __restrict__ D,
    const float* __restrict__ g2, const float* __restrict__ b2,
    int M, int N, int K, int act)
{
    extern __shared__ float smem[];
    float* sA = smem;
    float* sB = smem + 2 * A_BUF;

    const int tid  = threadIdx.x;
    const int warp = tid >> 5;
    const int lane = tid & 31;
    const int grp  = lane >> 2;
    const int t4   = lane & 3;
    const int wm   = warp >> 2;     // 0..1 -> 64 M rows
    const int wn   = warp & 3;      // 0..3 -> 32 N cols
    const int brow = blockIdx.y * 128;
    const int bcol = blockIdx.x * 128;

    const uint32_t sA_u = (uint32_t)__cvta_generic_to_shared(sA);
    const uint32_t sB_u = (uint32_t)__cvta_generic_to_shared(sB);
    const int KT = K >> 5;

    // ldmatrix A lane-role offsets (validated: identical rel_err)
    const int a_row = ((lane >> 3) & 1) * 8 + (lane & 7);  // mats 0/1: rows +0/+8
    const int a_col = (lane >> 4) * 4;                     // mats 2/3: k+4

    auto load_tile = [&](int kt, int buf) {
        const int k0 = kt << 5;
        #pragma unroll
        for (int it = 0; it < 4; it++) {
            const int idx = it * 256 + tid;
            const int r = idx >> 3, c = idx & 7;
            cp_async16(sA_u + (buf * A_BUF + r * AS_STRIDE + c * 4) * 4,
                       &A[(size_t)(brow + r) * K + k0 + c * 4]);
        }
        #pragma unroll
        for (int it = 0; it < 4; it++) {
            const int idx = it * 256 + tid;
            const int kr = idx >> 5, c = idx & 31;
            cp_async16(sB_u + (buf * B_BUF + kr * BS_STRIDE + c * 4) * 4,
                       &B[(size_t)(k0 + kr) * N + bcol + c * 4]);
        }
        cp_commit();
    };

    float acc[4][4][4];
    #pragma unroll
    for (int i = 0; i < 4; i++)
        #pragma unroll
        for (int j = 0; j < 4; j++)
            #pragma unroll
            for (int q = 0; q < 4; q++) acc[i][j][q] = 0.0f;

    load_tile(0, 0);

    for (int kt = 0; kt < KT; kt++) {
        if (kt + 1 < KT) { load_tile(kt + 1, (kt + 1) & 1); cp_wait<1>(); }
        else             { cp_wait<0>(); }
        __syncthreads();

        const uint32_t Ab_u = sA_u + ((kt & 1) * A_BUF) * 4;
        const float*   Bb   = sB + (kt & 1) * B_BUF;

        #pragma unroll
        for (int kk = 0; kk < 4; kk++) {
            const int kb = kk * 8;
            uint32_t af[4][4], bf[4][2];
            #pragma unroll
            for (int i = 0; i < 4; i++) {
                const int m0 = wm * 64 + i * 16;
                ldsm_x4(af[i][0], af[i][1], af[i][2], af[i][3],
                        Ab_u + ((m0 + a_row) * AS_STRIDE + kb + a_col) * 4);
            }
            #pragma unroll
            for (int j = 0; j < 4; j++) {
                const int n0 = wn * 32 + j * 8 + grp;
                bf[j][0] = __float_as_uint(Bb[(kb + t4    ) * BS_STRIDE + n0]);
                bf[j][1] = __float_as_uint(Bb[(kb + t4 + 4) * BS_STRIDE + n0]);
            }
            #pragma unroll
            for (int i = 0; i < 4; i++)
                #pragma unroll
                for (int j = 0; j < 4; j++)
                    mma_tf32(acc[i][j], af[i], bf[j]);
        }
        __syncthreads();
    }

    if (act == 2) {
        // ---- fused epilogue: x2 = acc + bias + res -> C and smem; LN -> D ----
        float* sx = smem;   // tile buffers are dead; reuse as [128][SX_STRIDE]
        #pragma unroll
        for (int i = 0; i < 4; i++) {
            const int rl0 = wm * 64 + i * 16 + grp;
            #pragma unroll
            for (int j = 0; j < 4; j++) {
                const int col = wn * 32 + j * 8 + 2 * t4;
                const float b0 = bias[col], b1 = bias[col + 1];
                #pragma unroll
                for (int half = 0; half < 2; half++) {
                    const int rl = rl0 + half * 8;
                    const int r  = brow + rl;
                    const float2 rr = *(const float2*)&res[(size_t)r * N + col];
                    const float v0 = acc[i][j][half * 2 + 0] + b0 + rr.x;
                    const float v1 = acc[i][j][half * 2 + 1] + b1 + rr.y;
                    *(float2*)&C[(size_t)r * N + col] = make_float2(v0, v1);
                    *(float2*)&sx[rl * SX_STRIDE + col] = make_float2(v0, v1);
                }
            }
        }
        __syncthreads();
        // pass 2: LN per row; warp handles 16 rows, lane = channel quad
        const float4 g4 = *(const float4*)&g2[lane * 4];
        const float4 b4 = *(const float4*)&b2[lane * 4];
        #pragma unroll
        for (int rr2 = 0; rr2 < 16; rr2++) {
            const int rl = warp * 16 + rr2;
            const float4 v = *(const float4*)&sx[rl * SX_STRIDE + lane * 4];
            float s  = v.x + v.y + v.z + v.w;
            float q  = v.x * v.x + v.y * v.y + v.z * v.z + v.w * v.w;
            #pragma unroll
            for (int o = 16; o > 0; o >>= 1) {
                s += __shfl_xor_sync(0xffffffffu, s, o);
                q += __shfl_xor_sync(0xffffffffu, q, o);
            }
            const float mean = s * (1.0f / CC);
            const float var  = q * (1.0f / CC) - mean * mean;
            const float rstd = rsqrtf(var + EPS);
            float4 o4;
            o4.x = (v.x - mean) * rstd * g4.x + b4.x;
            o4.y = (v.y - mean) * rstd * g4.y + b4.y;
            o4.z = (v.z - mean) * rstd * g4.z + b4.z;
            o4.w = (v.w - mean) * rstd * g4.w + b4.w;
            *(float4*)&D[(size_t)(brow + rl) * CC + lane * 4] = o4;
        }
        return;
    }

    #pragma unroll
    for (int i = 0; i < 4; i++) {
        const int r0 = brow + wm * 64 + i * 16 + grp;
        #pragma unroll
        for (int j = 0; j < 4; j++) {
            const int col = bcol + wn * 32 + j * 8 + 2 * t4;
            const float b0 = bias[col], b1 = bias[col + 1];
            #pragma unroll
            for (int half = 0; half < 2; half++) {
                const int r = r0 + half * 8;
                float v0 = acc[i][j][half * 2 + 0] + b0;
                float v1 = acc[i][j][half * 2 + 1] + b1;
                if (act == 1) { v0 = gelu_exact(v0); v1 = gelu_exact(v1); }
                if (res) {
                    const float2 rr = *(const float2*)&res[(size_t)r * N + col];
                    v0 += rr.x; v1 += rr.y;
                }
                *(float2*)&C[(size_t)r * N + col] = make_float2(v0, v1);
            }
        }
    }
}

// ------- deformable sampling + fused softmax; 1 warp per token, float4 ------
__global__ __launch_bounds__(128) void dcn_sample_kernel(
    const float* __restrict__ xp, const float* __restrict__ om,
    float* __restrict__ y)
{
    const int tt   = threadIdx.x >> 5;
    const int lane = threadIdx.x & 31;
    const int tok  = blockIdx.x * 4 + tt;
    const int n  = tok / (HH * WW);
    const int hw = tok % (HH * WW);
    const int h = hw / WW, w = hw % WW;

    __shared__ float s_om[4][216];
    const float* src = om + (size_t)tok * NOM;
    for (int i = lane; i < 216; i += 32) s_om[tt][i] = src[i];
    __syncwarp();

    if (lane < GG) {
        float* p = &s_om[tt][144 + lane * KK];
        float mx = -1e30f;
        #pragma unroll
        for (int k = 0; k < KK; k++) mx = fmaxf(mx, p[k]);
        float s = 0.0f, e[KK];
        #pragma unroll
        for (int k = 0; k < KK; k++) { e[k] = __expf(p[k] - mx); s += e[k]; }
        const float inv = 1.0f / s;
        #pragma unroll
        for (int k = 0; k < KK; k++) p[k] = e[k] * inv;
    }
    __syncwarp();

    const int g  = lane >> 2;
    const int c4 = lane & 3;
    const float* base = xp + ((size_t)n * HH * WW) * CC + g * GC + c4 * 4;
    float4 acc = make_float4(0.f, 0.f, 0.f, 0.f);

    #pragma unroll
    for (int k = 0; k < KK; k++) {
        const float ox = s_om[tt][(g * KK + k) * 2 + 0];
        const float oy = s_om[tt][(g * KK + k) * 2 + 1];
        const float mw = s_om[tt][144 + g * KK + k];
        const float px = (float)(w + 1 + (k / 3) - 1) + ox;
        const float py = (float)(h + 1 + (k % 3) - 1) + oy;
        const float x0f = floorf(px), y0f = floorf(py);
        const float tx = px - x0f, ty = py - y0f;
        const int x0 = (int)x0f, y0 = (int)y0f;

        const bool yi0 = (y0 >= 1) & (y0 <= HH);
        const bool yi1 = (y0 + 1 >= 1) & (y0 + 1 <= HH);
        const bool xi0 = (x0 >= 1) & (x0 <= WW);
        const bool xi1 = (x0 + 1 >= 1) & (x0 + 1 <= WW);

        float4 v00 = make_float4(0,0,0,0), v01 = v00, v10 = v00, v11 = v00;
        if (yi0 & xi0) v00 = *(const float4*)&base[((size_t)(y0 - 1) * WW + (x0 - 1)) * CC];
        if (yi0 & xi1) v01 = *(const float4*)&base[((size_t)(y0 - 1) * WW + (x0    )) * CC];
        if (yi1 & xi0) v10 = *(const float4*)&base[((size_t)(y0    ) * WW + (x0 - 1)) * CC];
        if (yi1 & xi1) v11 = *(const float4*)&base[((size_t)(y0    ) * WW + (x0    )) * CC];

        const float w00 = mw * (1.f - ty) * (1.f - tx);
        const float w01 = mw * (1.f - ty) * tx;
        const float w10 = mw * ty * (1.f - tx);
        const float w11 = mw * ty * tx;
        acc.x += w00 * v00.x + w01 * v01.x + w10 * v10.x + w11 * v11.x;
        acc.y += w00 * v00.y + w01 * v01.y + w10 * v10.y + w11 * v11.y;
        acc.z += w00 * v00.z + w01 * v01.z + w10 * v10.z + w11 * v11.z;
        acc.w += w00 * v00.w + w01 * v01.w + w10 * v10.w + w11 * v11.w;
    }
    *(float4*)&y[(size_t)tok * CC + g * GC + c4 * 4] = acc;
}

// ---------------------------------------------------------------------------
extern "C" void kernel_launch(void* const* d_in, const int* in_sizes, int n_in,
                              void* d_out, int out_size)
{
    const float* x      = (const float*)d_in[0];
    const float* ln1_g  = (const float*)d_in[1];
    const float* ln1_b  = (const float*)d_in[2];
    const float* in_w   = (const float*)d_in[3];
    const float* in_b   = (const float*)d_in[4];
    const float* dw_k   = (const float*)d_in[5];
    const float* dw_b   = (const float*)d_in[6];
    const float* dwln_g = (const float*)d_in[7];
    const float* dwln_b = (const float*)d_in[8];
    const float* off_w  = (const float*)d_in[9];
    const float* off_b  = (const float*)d_in[10];
    const float* mask_w = (const float*)d_in[11];
    const float* mask_b = (const float*)d_in[12];
    const float* out_w  = (const float*)d_in[13];
    const float* out_b  = (const float*)d_in[14];
    const float* ln2_g  = (const float*)d_in[15];
    const float* ln2_b  = (const float*)d_in[16];
    const float* fc1_w  = (const float*)d_in[17];
    const float* fc1_b  = (const float*)d_in[18];
    const float* fc2_w  = (const float*)d_in[19];
    const float* fc2_b  = (const float*)d_in[20];
    float* out = (float*)d_out;

    float *xn, *xp, *x1, *omp, *yp, *x2, *hp, *h1, *wcat, *bcat;
    cudaGetSymbolAddress((void**)&xn,   g_xn);
    cudaGetSymbolAddress((void**)&xp,   g_xp);
    cudaGetSymbolAddress((void**)&x1,   g_x1);
    cudaGetSymbolAddress((void**)&omp,  g_om);
    cudaGetSymbolAddress((void**)&yp,   g_y);
    cudaGetSymbolAddress((void**)&x2,   g_x2);
    cudaGetSymbolAddress((void**)&hp,   g_h);
    cudaGetSymbolAddress((void**)&h1,   g_h1);
    cudaGetSymbolAddress((void**)&wcat, g_wcat);
    cudaGetSymbolAddress((void**)&bcat, g_bcat);

    static bool attr_done = false;
    if (!attr_done) {
        cudaFuncSetAttribute(gemm_tf32_db_kernel,
                             cudaFuncAttributeMaxDynamicSharedMemorySize,
                             GEMM_SMEM_BYTES);
        attr_done = true;
    }

    const int MROW = NTOK / 128;
    const dim3 gemm128(1, MROW);
    const dim3 gemm256(2, MROW);
    const dim3 gemm512(4, MROW);

    // 0. pack offset|mask weights (idempotent)
    prep_offmask_kernel<<<CC, NOM>>>(off_w, off_b, mask_w, mask_b, wcat, bcat);
    // 1. xn = LN1(x)
    ln_v4_kernel<<<NTOK / 8, 256>>>(x, ln1_g, ln1_b, xn);
    // 2. xp = xn @ in_w + in_b
    gemm_tf32_db_kernel<<<gemm128, 256, GEMM_SMEM_BYTES>>>(
        xn, in_w, in_b, nullptr, xp, nullptr, nullptr, nullptr, NTOK, CC, CC, 0);
    // 3. x1 = gelu(LN(dwconv(xn)))
    dwconv_ln_gelu_v4_kernel<<<NTOK / 8, 256>>>(xn, dw_k, dw_b, dwln_g, dwln_b, x1);
    // 4. [offset | mask logits] = x1 @ wcat + bcat
    gemm_tf32_db_kernel<<<gemm256, 256, GEMM_SMEM_BYTES>>>(
        x1, wcat, bcat, nullptr, omp, nullptr, nullptr, nullptr, NTOK, NOM, CC, 0);
    // 5. y = deformable sample(xp, offsets, softmax(logits))
    dcn_sample_kernel<<<NTOK / 4, 128>>>(xp, omp, yp);
    // 6. x2 = y @ out_w + out_b + x ; h = LN2(x2)  (fused epilogue)
    gemm_tf32_db_kernel<<<gemm128, 256, GEMM_SMEM_BYTES>>>(
        yp, out_w, out_b, x, x2, hp, ln2_g, ln2_b, NTOK, CC, CC, 2);
    // 7. h1 = gelu(h @ fc1_w + fc1_b)
    gemm_tf32_db_kernel<<<gemm512, 256, GEMM_SMEM_BYTES>>>(
        hp, fc1_w, fc1_b, nullptr, h1, nullptr, nullptr, nullptr, NTOK, HID, CC, 1);
    // 8. out = h1 @ fc2_w + fc2_b + x2
    gemm_tf32_db_kernel<<<gemm128, 256, GEMM_SMEM_BYTES>>>(
        h1, fc2_w, fc2_b, x2, out, nullptr, nullptr, nullptr, NTOK, CC, HID, 0);
}